// round 5
// baseline (speedup 1.0000x reference)
#include <cuda_runtime.h>
#include <cuda_bf16.h>

// NBVLoss: weighted BCE full reduction, single fused kernel.
//   loss = 1.6 * sum_{t==1} bce + 0.4 * sum_{t==0} bce
// t is exactly 0/1 -> one log per element:
//   contrib = -w * max(__logf(x), -100),  (x,w) = t ? (p,1.6) : (1-p,0.4)
//
// R5: 128 threads/block, 8 CTAs/SM (64-reg budget -> no spill), manual
// unroll-4 with all 8 LDG.128 front-batched per iteration (MLP_p1 = 8)
// to deepen the per-warp L1tex queue. Two accumulators split the FADD chain.
//
// Per-block double partials; last-arriving block reduces them in a fixed
// order (deterministic) and resets the arrival counter for graph replay.

constexpr int BLOCKS  = 1184;   // 148 SMs * 8 CTAs
constexpr int THREADS = 128;
constexpr float LOG_CLAMP = -100.0f;

__device__ double g_partial[BLOCKS];
__device__ unsigned int g_arrive_count;   // zero-init; reset by last block

__device__ __forceinline__ float bce_w(float p, float t) {
    bool one = (t != 0.0f);
    float x = one ? p    : (1.0f - p);
    float w = one ? 1.6f : 0.4f;
    // __logf(0) = -inf -> clamped to -100, matching jnp.clip(log(.), -100)
    return -w * fmaxf(__logf(x), LOG_CLAMP);
}

__device__ __forceinline__ float bce4(float4 pv, float4 tv) {
    return bce_w(pv.x, tv.x) + bce_w(pv.y, tv.y)
         + bce_w(pv.z, tv.z) + bce_w(pv.w, tv.w);
}

__global__ void __launch_bounds__(THREADS, 8)
bce_fused_kernel(const float4* __restrict__ pred,
                 const float4* __restrict__ targ,
                 int n4, int n_tail_base, int n_total,
                 float* __restrict__ out)
{
    const int stride = BLOCKS * THREADS;
    int idx = blockIdx.x * THREADS + threadIdx.x;

    float acc0 = 0.0f, acc1 = 0.0f;

    // Unroll-4: 8 front-batched LDG.128 per iteration.
    for (; idx + 3 * stride < n4; idx += 4 * stride) {
        float4 p0 = __ldcs(&pred[idx]);
        float4 p1 = __ldcs(&pred[idx +     stride]);
        float4 p2 = __ldcs(&pred[idx + 2 * stride]);
        float4 p3 = __ldcs(&pred[idx + 3 * stride]);
        float4 t0 = __ldcs(&targ[idx]);
        float4 t1 = __ldcs(&targ[idx +     stride]);
        float4 t2 = __ldcs(&targ[idx + 2 * stride]);
        float4 t3 = __ldcs(&targ[idx + 3 * stride]);
        acc0 += bce4(p0, t0);
        acc1 += bce4(p1, t1);
        acc0 += bce4(p2, t2);
        acc1 += bce4(p3, t3);
    }
    // Remainder float4 iterations.
    for (; idx < n4; idx += stride) {
        float4 pv = __ldcs(&pred[idx]);
        float4 tv = __ldcs(&targ[idx]);
        acc0 += bce4(pv, tv);
    }
    float local = acc0 + acc1;

    // Scalar tail (n not divisible by 4) — one thread, deterministic.
    if (blockIdx.x == 0 && threadIdx.x == 0) {
        const float* ps = (const float*)pred;
        const float* ts = (const float*)targ;
        for (int i = n_tail_base; i < n_total; i++)
            local += bce_w(ps[i], ts[i]);
    }

    // Warp reduce (float), then cross-warp in double (fixed order per block).
    #pragma unroll
    for (int off = 16; off > 0; off >>= 1)
        local += __shfl_down_sync(0xFFFFFFFFu, local, off);

    __shared__ double s_warp[THREADS / 32];
    __shared__ bool s_is_last;
    int wid = threadIdx.x >> 5;
    int lid = threadIdx.x & 31;
    if (lid == 0) s_warp[wid] = (double)local;
    __syncthreads();

    if (threadIdx.x == 0) {
        double acc = 0.0;
        #pragma unroll
        for (int w = 0; w < THREADS / 32; w++) acc += s_warp[w];
        g_partial[blockIdx.x] = acc;
        __threadfence();
        unsigned int prev = atomicAdd(&g_arrive_count, 1u);
        s_is_last = (prev == (unsigned int)(BLOCKS - 1));
    }
    __syncthreads();

    if (s_is_last) {
        // Last block reduces all partials in a FIXED order -> deterministic.
        __shared__ double s_fin[THREADS];
        double v = 0.0;
        for (int i = threadIdx.x; i < BLOCKS; i += THREADS)
            v += g_partial[i];
        s_fin[threadIdx.x] = v;
        __syncthreads();
        #pragma unroll
        for (int off = THREADS / 2; off > 0; off >>= 1) {
            if (threadIdx.x < off) s_fin[threadIdx.x] += s_fin[threadIdx.x + off];
            __syncthreads();
        }
        if (threadIdx.x == 0) {
            out[0] = (float)s_fin[0];
            g_arrive_count = 0;   // reset for next graph replay
        }
    }
}

extern "C" void kernel_launch(void* const* d_in, const int* in_sizes, int n_in,
                              void* d_out, int out_size)
{
    const float4* pred = (const float4*)d_in[0];
    const float4* targ = (const float4*)d_in[1];
    float* out = (float*)d_out;

    int n  = in_sizes[0];        // 16384*4096 = 67108864
    int n4 = n >> 2;
    int tail_base = n4 << 2;

    bce_fused_kernel<<<BLOCKS, THREADS>>>(pred, targ, n4, tail_base, n, out);
}

// round 6
// speedup vs baseline: 1.0057x; 1.0057x over previous
#include <cuda_runtime.h>
#include <cuda_bf16.h>

// NBVLoss: weighted BCE full reduction, single fused kernel.
//   loss = 1.6 * sum_{t==1} bce + 0.4 * sum_{t==0} bce
// t is exactly 0/1 -> one log per element:
//   contrib = -w * max(__logf(x), -100),  (x,w) = t ? (p,1.6) : (1-p,0.4)
//
// R6: R4's winning shape (256 thr, 8 CTAs/SM, one wave of 1184 blocks)
// + moderate front-batching: unroll-2 with 4 LDG.128 issued back-to-back,
// dual accumulators. Live regs ~28-30 -> fits 32-reg/8-CTA budget.
//
// Per-block double partials; last-arriving block reduces them in a fixed
// order (deterministic) and resets the arrival counter for graph replay.

constexpr int BLOCKS  = 1184;   // 148 SMs * 8 CTAs
constexpr int THREADS = 256;
constexpr float LOG_CLAMP = -100.0f;

__device__ double g_partial[BLOCKS];
__device__ unsigned int g_arrive_count;   // zero-init; reset by last block

__device__ __forceinline__ float bce_w(float p, float t) {
    bool one = (t != 0.0f);
    float x = one ? p    : (1.0f - p);
    float w = one ? 1.6f : 0.4f;
    // __logf(0) = -inf -> clamped to -100, matching jnp.clip(log(.), -100)
    return -w * fmaxf(__logf(x), LOG_CLAMP);
}

__device__ __forceinline__ float bce4(float4 pv, float4 tv) {
    return bce_w(pv.x, tv.x) + bce_w(pv.y, tv.y)
         + bce_w(pv.z, tv.z) + bce_w(pv.w, tv.w);
}

__global__ void __launch_bounds__(THREADS, 8)
bce_fused_kernel(const float4* __restrict__ pred,
                 const float4* __restrict__ targ,
                 int n4, int n_tail_base, int n_total,
                 float* __restrict__ out)
{
    const int stride = BLOCKS * THREADS;
    int idx = blockIdx.x * THREADS + threadIdx.x;

    float acc0 = 0.0f, acc1 = 0.0f;

    // Unroll-2: 4 front-batched LDG.128 per iteration.
    for (; idx + stride < n4; idx += 2 * stride) {
        float4 p0 = __ldcs(&pred[idx]);
        float4 t0 = __ldcs(&targ[idx]);
        float4 p1 = __ldcs(&pred[idx + stride]);
        float4 t1 = __ldcs(&targ[idx + stride]);
        acc0 += bce4(p0, t0);
        acc1 += bce4(p1, t1);
    }
    // Remainder float4 iteration.
    if (idx < n4) {
        float4 pv = __ldcs(&pred[idx]);
        float4 tv = __ldcs(&targ[idx]);
        acc0 += bce4(pv, tv);
    }
    float local = acc0 + acc1;

    // Scalar tail (n not divisible by 4) — one thread, deterministic.
    if (blockIdx.x == 0 && threadIdx.x == 0) {
        const float* ps = (const float*)pred;
        const float* ts = (const float*)targ;
        for (int i = n_tail_base; i < n_total; i++)
            local += bce_w(ps[i], ts[i]);
    }

    // Warp reduce (float), then cross-warp in double (fixed order per block).
    #pragma unroll
    for (int off = 16; off > 0; off >>= 1)
        local += __shfl_down_sync(0xFFFFFFFFu, local, off);

    __shared__ double s_warp[THREADS / 32];
    __shared__ bool s_is_last;
    int wid = threadIdx.x >> 5;
    int lid = threadIdx.x & 31;
    if (lid == 0) s_warp[wid] = (double)local;
    __syncthreads();

    if (threadIdx.x == 0) {
        double acc = 0.0;
        #pragma unroll
        for (int w = 0; w < THREADS / 32; w++) acc += s_warp[w];
        g_partial[blockIdx.x] = acc;
        __threadfence();
        unsigned int prev = atomicAdd(&g_arrive_count, 1u);
        s_is_last = (prev == (unsigned int)(BLOCKS - 1));
    }
    __syncthreads();

    if (s_is_last) {
        // Last block reduces all partials in a FIXED order -> deterministic.
        __shared__ double s_fin[THREADS];
        double v = 0.0;
        for (int i = threadIdx.x; i < BLOCKS; i += THREADS)
            v += g_partial[i];
        s_fin[threadIdx.x] = v;
        __syncthreads();
        #pragma unroll
        for (int off = THREADS / 2; off > 0; off >>= 1) {
            if (threadIdx.x < off) s_fin[threadIdx.x] += s_fin[threadIdx.x + off];
            __syncthreads();
        }
        if (threadIdx.x == 0) {
            out[0] = (float)s_fin[0];
            g_arrive_count = 0;   // reset for next graph replay
        }
    }
}

extern "C" void kernel_launch(void* const* d_in, const int* in_sizes, int n_in,
                              void* d_out, int out_size)
{
    const float4* pred = (const float4*)d_in[0];
    const float4* targ = (const float4*)d_in[1];
    float* out = (float*)d_out;

    int n  = in_sizes[0];        // 16384*4096 = 67108864
    int n4 = n >> 2;
    int tail_base = n4 << 2;

    bce_fused_kernel<<<BLOCKS, THREADS>>>(pred, targ, n4, tail_base, n, out);
}

// round 7
// speedup vs baseline: 1.0214x; 1.0155x over previous
#include <cuda_runtime.h>
#include <cuda_bf16.h>

// NBVLoss: weighted BCE full reduction, single fused kernel. FINAL (R4 config).
//   loss = 1.6 * sum_{t==1} bce + 0.4 * sum_{t==0} bce
//   bce  = -(t*max(log p, -100) + (1-t)*max(log(1-p), -100))
//
// t is exactly 0/1 -> one log per element:
//   contrib = -w * max(__logf(x), -100),  (x,w) = t ? (p,1.6) : (1-p,0.4)
//
// Why this shape (evidence from R1-R6):
//  - Pure HBM-streaming problem: 536.9 MB read, 4 B written. Every loop/
//    occupancy/unroll variant plateaus at 6.1-6.4 TB/s (LTS path ceiling),
//    so ~83 us is the roofline; this config benchmarked fastest (83.1 us).
//  - __launch_bounds__(256, 8): caps regs at 32 -> 8 CTAs/SM -> grid 1184
//    = ONE wave on 148 SMs (R2 showed a 7-CTA straggler wave costs +16 us).
//  - No manual unroll: compiler schedule at this shape beat MLP_p1=4/8
//    variants (R5/R6).
//  - One log instead of two: halves MUFU pressure (issue 50%->27%), -2 us.
//  - Fused last-block finalize: removes the second launch; deterministic
//    (fixed-order reduction; arrival counter self-resets for graph replay).

constexpr int BLOCKS  = 1184;   // 148 SMs * 8 CTAs
constexpr int THREADS = 256;
constexpr float LOG_CLAMP = -100.0f;

__device__ double g_partial[BLOCKS];
__device__ unsigned int g_arrive_count;   // zero-init; reset by last block

__device__ __forceinline__ float bce_w(float p, float t) {
    bool one = (t != 0.0f);
    float x = one ? p    : (1.0f - p);
    float w = one ? 1.6f : 0.4f;
    // __logf(0) = -inf -> clamped to -100, matching jnp.clip(log(.), -100)
    float lx = fmaxf(__logf(x), LOG_CLAMP);
    return -w * lx;
}

__global__ void __launch_bounds__(THREADS, 8)
bce_fused_kernel(const float4* __restrict__ pred,
                 const float4* __restrict__ targ,
                 int n4, int n_tail_base, int n_total,
                 float* __restrict__ out)
{
    float local = 0.0f;

    int idx = blockIdx.x * THREADS + threadIdx.x;
    const int stride = BLOCKS * THREADS;
    for (; idx < n4; idx += stride) {
        float4 pv = __ldcs(&pred[idx]);   // streaming: read-once data
        float4 tv = __ldcs(&targ[idx]);
        local += bce_w(pv.x, tv.x);
        local += bce_w(pv.y, tv.y);
        local += bce_w(pv.z, tv.z);
        local += bce_w(pv.w, tv.w);
    }

    // Scalar tail (n not divisible by 4) — one thread, deterministic.
    if (blockIdx.x == 0 && threadIdx.x == 0) {
        const float* ps = (const float*)pred;
        const float* ts = (const float*)targ;
        for (int i = n_tail_base; i < n_total; i++)
            local += bce_w(ps[i], ts[i]);
    }

    // Warp reduce (float), then cross-warp in double (fixed order per block).
    #pragma unroll
    for (int off = 16; off > 0; off >>= 1)
        local += __shfl_down_sync(0xFFFFFFFFu, local, off);

    __shared__ double s_warp[THREADS / 32];
    __shared__ bool s_is_last;
    int wid = threadIdx.x >> 5;
    int lid = threadIdx.x & 31;
    if (lid == 0) s_warp[wid] = (double)local;
    __syncthreads();

    if (threadIdx.x == 0) {
        double acc = 0.0;
        #pragma unroll
        for (int w = 0; w < THREADS / 32; w++) acc += s_warp[w];
        g_partial[blockIdx.x] = acc;
        // Make the partial globally visible before signaling arrival.
        __threadfence();
        unsigned int prev = atomicAdd(&g_arrive_count, 1u);
        s_is_last = (prev == (unsigned int)(BLOCKS - 1));
    }
    __syncthreads();

    if (s_is_last) {
        // Last block reduces all partials in a FIXED order -> deterministic.
        __shared__ double s_fin[THREADS];
        double v = 0.0;
        for (int i = threadIdx.x; i < BLOCKS; i += THREADS)
            v += g_partial[i];
        s_fin[threadIdx.x] = v;
        __syncthreads();
        #pragma unroll
        for (int off = THREADS / 2; off > 0; off >>= 1) {
            if (threadIdx.x < off) s_fin[threadIdx.x] += s_fin[threadIdx.x + off];
            __syncthreads();
        }
        if (threadIdx.x == 0) {
            out[0] = (float)s_fin[0];
            g_arrive_count = 0;   // reset for next graph replay
        }
    }
}

extern "C" void kernel_launch(void* const* d_in, const int* in_sizes, int n_in,
                              void* d_out, int out_size)
{
    const float4* pred = (const float4*)d_in[0];
    const float4* targ = (const float4*)d_in[1];
    float* out = (float*)d_out;

    int n  = in_sizes[0];        // 16384*4096 = 67108864
    int n4 = n >> 2;
    int tail_base = n4 << 2;

    bce_fused_kernel<<<BLOCKS, THREADS>>>(pred, targ, n4, tail_base, n, out);
}